// round 13
// baseline (speedup 1.0000x reference)
#include <cuda_runtime.h>
#include <cuda_bf16.h>

// ---------------------------------------------------------------------------
// GraphConvNet: B=8, V=2048, D=3, CL1(K=6,F=64), CL2(K=5,F=128), FC 512, 256
// fp32 throughout. Chebyshev L-streams at HBM rate; GEMMs via packed f32x2
// with double-buffered smem and pre-duplicated B operands.
// ---------------------------------------------------------------------------

#define BATCH 8
#define NV    2048
#define NROWS (BATCH * NV)      // 16384

// scratch (device globals; no allocation allowed)
// conv1 basis stored as 18 slabs of [NROWS]; slab id = fin*6 + k (torch order)
__device__ float g_xk1[(size_t)18 * NROWS];
__device__ float g_z[(size_t)5 * NROWS * 64];        // conv2 basis slabs z0..z4, [row][64]
__device__ float g_xk2[(size_t)NROWS * 320];         // packed conv2 basis [row][fin*5+k]
__device__ float g_y2[(size_t)NROWS * 128];
__device__ float g_h1[(size_t)NROWS * 512];

#define ZSLAB ((size_t)NROWS * 64)

// ------------------------- f32x2 packed-FMA helpers ------------------------
__device__ __forceinline__ void fma2(unsigned long long& c,
                                     unsigned long long a, unsigned long long b) {
    asm("fma.rn.f32x2 %0, %1, %2, %0;" : "+l"(c) : "l"(a), "l"(b));
}
__device__ __forceinline__ float2 unpk2(unsigned long long v) {
    float2 f;
    asm("mov.b64 {%0, %1}, %2;" : "=f"(f.x), "=f"(f.y) : "l"(v));
    return f;
}

// ------------------------- transpose x [B,D,V] -> xk1 slab (d*6+0) ---------
__global__ void __launch_bounds__(256) k_xpose(const float* __restrict__ x,
                                               float* __restrict__ xk1) {
    int idx = blockIdx.x * 256 + threadIdx.x;           // over 8*3*2048
    if (idx >= BATCH * 3 * NV) return;
    int v = idx & (NV - 1);
    int d = (idx >> 11) % 3;
    int b = idx / (3 * NV);
    xk1[(size_t)(d * 6) * NROWS + b * NV + v] = x[idx];
}

// ------------------------- conv1 Chebyshev step (Fin=3) --------------------
// slab(f,k) <- alpha * L @ slab(f,k-1) + beta * slab(f,k-2), warp per row
__global__ void __launch_bounds__(256) k_cheby(
    const float* __restrict__ L, float* __restrict__ xk,
    int kIdx, float alpha, float beta) {
    __shared__ __align__(16) float sx[3][NV];
    const int tid = threadIdx.x;
    const int b = blockIdx.x >> 8;                       // 256 blocks per batch
    const size_t bV = (size_t)b * NV;

    #pragma unroll
    for (int f = 0; f < 3; f++) {
        const float* src = xk + (size_t)(f * 6 + kIdx - 1) * NROWS + bV;
        for (int c = tid * 4; c < NV; c += 1024)
            *reinterpret_cast<float4*>(&sx[f][c]) =
                *reinterpret_cast<const float4*>(&src[c]);
    }
    __syncthreads();

    const int warp = tid >> 5, lane = tid & 31;
    const int row = blockIdx.x * 8 + warp;               // global row 0..16383
    const float4* Lr = reinterpret_cast<const float4*>(L + (size_t)row * NV);
    float a0 = 0.f, a1 = 0.f, a2 = 0.f;
    #pragma unroll
    for (int it = 0; it < 16; it++) {
        const int c4 = it * 32 + lane;
        const float4 lv = Lr[c4];
        const float4 x0 = reinterpret_cast<const float4*>(sx[0])[c4];
        const float4 x1 = reinterpret_cast<const float4*>(sx[1])[c4];
        const float4 x2 = reinterpret_cast<const float4*>(sx[2])[c4];
        a0 += lv.x * x0.x + lv.y * x0.y + lv.z * x0.z + lv.w * x0.w;
        a1 += lv.x * x1.x + lv.y * x1.y + lv.z * x1.z + lv.w * x1.w;
        a2 += lv.x * x2.x + lv.y * x2.y + lv.z * x2.z + lv.w * x2.w;
    }
    #pragma unroll
    for (int off = 16; off > 0; off >>= 1) {
        a0 += __shfl_down_sync(0xffffffffu, a0, off);
        a1 += __shfl_down_sync(0xffffffffu, a1, off);
        a2 += __shfl_down_sync(0xffffffffu, a2, off);
    }
    if (lane == 0) {
        float acc[3] = {a0, a1, a2};
        #pragma unroll
        for (int f = 0; f < 3; f++) {
            float p = 0.f;
            if (beta != 0.f)
                p = xk[(size_t)(f * 6 + kIdx - 2) * NROWS + row];
            xk[(size_t)(f * 6 + kIdx) * NROWS + row] = alpha * acc[f] + beta * p;
        }
    }
}

// ------------------------- conv1 linear: z0 = relu(xk1 @ W1^T + b1) --------
// thread per row; weights transposed into smem as sW[j][fo]
__global__ void __launch_bounds__(256) k_conv1_lin(
    const float* __restrict__ xk, const float* __restrict__ W,
    const float* __restrict__ bias, float* __restrict__ z0) {
    __shared__ float sW[18 * 64];
    __shared__ float sb[64];
    const int tid = threadIdx.x;
    for (int i = tid; i < 18 * 64; i += 256) {
        int fo = i / 18, j = i % 18;
        sW[j * 64 + fo] = W[i];
    }
    if (tid < 64) sb[tid] = bias[tid];
    __syncthreads();

    const int row = blockIdx.x * 256 + tid;
    float acc[64];
    #pragma unroll
    for (int fo = 0; fo < 64; fo++) acc[fo] = sb[fo];
    #pragma unroll
    for (int j = 0; j < 18; j++) {
        const float xv = xk[(size_t)j * NROWS + row];
        #pragma unroll
        for (int fo = 0; fo < 64; fo++) acc[fo] += xv * sW[j * 64 + fo];
    }
    float* o = z0 + (size_t)row * 64;
    #pragma unroll
    for (int fo = 0; fo < 64; fo += 4) {
        float4 v;
        v.x = acc[fo]     > 0.f ? acc[fo]     : 0.f;
        v.y = acc[fo + 1] > 0.f ? acc[fo + 1] : 0.f;
        v.z = acc[fo + 2] > 0.f ? acc[fo + 2] : 0.f;
        v.w = acc[fo + 3] > 0.f ? acc[fo + 3] : 0.f;
        *reinterpret_cast<float4*>(&o[fo]) = v;
    }
}

// ------------------------- pack conv2 basis into [row, fin*5+k] ------------
__global__ void __launch_bounds__(256) k_pack2(const float* __restrict__ z,
                                               float* __restrict__ xk2) {
    size_t idx = (size_t)blockIdx.x * 256 + threadIdx.x;   // over 16384*64
    size_t row = idx >> 6;
    int fin = (int)(idx & 63);
    float* o = xk2 + row * 320 + fin * 5;
    #pragma unroll
    for (int k = 0; k < 5; k++) o[k] = z[(size_t)k * ZSLAB + idx];
}

// ------------------------- main GEMM tile kernel (v2) ----------------------
// C[M,N] tiles of 128x64, BK=16, double-buffered, B pre-duplicated for f32x2.
// WTRANS: B is W[N,K] row-major (ldb=K), used as B^T.
// RELUB: C = relu(A@B + bias[n]).  else: C = alpha*A@B + beta*P.
#define T_BM 128
#define T_BN 64
#define T_BK 16
#define ASTR 132      // floats per k-row of As (132*4=528B, 16B aligned)
#define BSTR2 66      // float2 per k-row of Bs (66*8=528B, 16B aligned)

template <bool WTRANS, bool RELUB>
__global__ void __launch_bounds__(256, 2) k_gemm(
    const float* __restrict__ A, int lda, size_t strideA,
    const float* __restrict__ B, int ldb, size_t strideB,
    float* __restrict__ C, int ldc, size_t strideC,
    const float* __restrict__ P, size_t strideP,
    float alpha, float beta, int K) {
    __shared__ __align__(16) float  As[2][T_BK * ASTR];
    __shared__ __align__(16) float2 Bs[2][T_BK * BSTR2];

    const int tid = threadIdx.x;
    const int bz = blockIdx.z;
    A += (size_t)bz * strideA;
    B += (size_t)bz * strideB;
    C += (size_t)bz * strideC;
    P += (size_t)bz * strideP;
    const int m0 = blockIdx.y * T_BM;
    const int n0 = blockIdx.x * T_BN;

    const int tx = tid & 15;   // 4 N-cols each
    const int ty = tid >> 4;   // 8 M-rows each

    unsigned long long acc[4][4];
    #pragma unroll
    for (int p = 0; p < 4; p++)
        #pragma unroll
        for (int j = 0; j < 4; j++) acc[p][j] = 0ull;

    const int arow = tid >> 2;           // 0..63
    const int acol = (tid & 3) * 4;      // 0,4,8,12
    const int brow = tid >> 4;           // 0..15
    const int bcol = (tid & 15) * 4;     // 0..60

    // ---- tile load/store helpers (inlined) ----
    #define LOAD_A(kt, v0, v1)                                                  \
        v0 = *reinterpret_cast<const float4*>(A + (size_t)(m0 + arow) * lda + (kt) + acol); \
        v1 = *reinterpret_cast<const float4*>(A + (size_t)(m0 + arow + 64) * lda + (kt) + acol);
    #define STORE_A(buf, v0, v1)                                                \
        As[buf][(acol + 0) * ASTR + arow] = v0.x;                               \
        As[buf][(acol + 1) * ASTR + arow] = v0.y;                               \
        As[buf][(acol + 2) * ASTR + arow] = v0.z;                               \
        As[buf][(acol + 3) * ASTR + arow] = v0.w;                               \
        As[buf][(acol + 0) * ASTR + arow + 64] = v1.x;                          \
        As[buf][(acol + 1) * ASTR + arow + 64] = v1.y;                          \
        As[buf][(acol + 2) * ASTR + arow + 64] = v1.z;                          \
        As[buf][(acol + 3) * ASTR + arow + 64] = v1.w;
    #define LOAD_B(kt, v)                                                       \
        if (WTRANS) v = *reinterpret_cast<const float4*>(B + (size_t)(n0 + arow) * ldb + (kt) + acol); \
        else        v = *reinterpret_cast<const float4*>(B + (size_t)((kt) + brow) * ldb + n0 + bcol);
    #define STORE_B(buf, v)                                                     \
        if (WTRANS) {                                                           \
            Bs[buf][(acol + 0) * BSTR2 + arow] = make_float2(v.x, v.x);         \
            Bs[buf][(acol + 1) * BSTR2 + arow] = make_float2(v.y, v.y);         \
            Bs[buf][(acol + 2) * BSTR2 + arow] = make_float2(v.z, v.z);         \
            Bs[buf][(acol + 3) * BSTR2 + arow] = make_float2(v.w, v.w);         \
        } else {                                                                \
            float4 lo = make_float4(v.x, v.x, v.y, v.y);                        \
            float4 hi = make_float4(v.z, v.z, v.w, v.w);                        \
            *reinterpret_cast<float4*>(&Bs[buf][brow * BSTR2 + bcol])     = lo; \
            *reinterpret_cast<float4*>(&Bs[buf][brow * BSTR2 + bcol + 2]) = hi; \
        }

    // prologue: tile 0 -> buf 0
    {
        float4 a0, a1, bv;
        LOAD_A(0, a0, a1)
        LOAD_B(0, bv)
        STORE_A(0, a0, a1)
        STORE_B(0, bv)
    }
    __syncthreads();

    const int nt = K / T_BK;
    int cur = 0;
    for (int t = 0; t < nt; t++) {
        float4 pa0, pa1, pb;
        const bool has = (t + 1) < nt;
        if (has) {
            const int ktn = (t + 1) * T_BK;
            LOAD_A(ktn, pa0, pa1)
            LOAD_B(ktn, pb)
        }
        const float*  Ac = As[cur];
        const float2* Bc = Bs[cur];
        #pragma unroll
        for (int k = 0; k < T_BK; k++) {
            const float* ap = &Ac[k * ASTR + ty * 8];
            const ulonglong2 a01 = *reinterpret_cast<const ulonglong2*>(ap);
            const ulonglong2 a23 = *reinterpret_cast<const ulonglong2*>(ap + 4);
            const ulonglong2* bp =
                reinterpret_cast<const ulonglong2*>(&Bc[k * BSTR2 + tx * 4]);
            const ulonglong2 b01 = bp[0];
            const ulonglong2 b23 = bp[1];
            fma2(acc[0][0], a01.x, b01.x); fma2(acc[0][1], a01.x, b01.y);
            fma2(acc[0][2], a01.x, b23.x); fma2(acc[0][3], a01.x, b23.y);
            fma2(acc[1][0], a01.y, b01.x); fma2(acc[1][1], a01.y, b01.y);
            fma2(acc[1][2], a01.y, b23.x); fma2(acc[1][3], a01.y, b23.y);
            fma2(acc[2][0], a23.x, b01.x); fma2(acc[2][1], a23.x, b01.y);
            fma2(acc[2][2], a23.x, b23.x); fma2(acc[2][3], a23.x, b23.y);
            fma2(acc[3][0], a23.y, b01.x); fma2(acc[3][1], a23.y, b01.y);
            fma2(acc[3][2], a23.y, b23.x); fma2(acc[3][3], a23.y, b23.y);
        }
        if (has) {
            STORE_A(cur ^ 1, pa0, pa1)
            STORE_B(cur ^ 1, pb)
        }
        __syncthreads();
        cur ^= 1;
    }

    // ---- epilogue ----
    const int gn = n0 + tx * 4;
    #pragma unroll
    for (int p = 0; p < 4; p++) {
        float rows[2][4];
        #pragma unroll
        for (int j = 0; j < 4; j++) {
            float2 f = unpk2(acc[p][j]);
            rows[0][j] = f.x;
            rows[1][j] = f.y;
        }
        #pragma unroll
        for (int h = 0; h < 2; h++) {
            const int gm = m0 + ty * 8 + 2 * p + h;
            float* crow = C + (size_t)gm * ldc + gn;
            if (RELUB) {
                float4 v;
                v.x = rows[h][0] + P[gn + 0];
                v.y = rows[h][1] + P[gn + 1];
                v.z = rows[h][2] + P[gn + 2];
                v.w = rows[h][3] + P[gn + 3];
                v.x = v.x > 0.f ? v.x : 0.f;
                v.y = v.y > 0.f ? v.y : 0.f;
                v.z = v.z > 0.f ? v.z : 0.f;
                v.w = v.w > 0.f ? v.w : 0.f;
                *reinterpret_cast<float4*>(crow) = v;
            } else if (beta != 0.f) {
                const float4 pr = *reinterpret_cast<const float4*>(
                    P + (size_t)gm * ldc + gn);
                float4 v;
                v.x = alpha * rows[h][0] + beta * pr.x;
                v.y = alpha * rows[h][1] + beta * pr.y;
                v.z = alpha * rows[h][2] + beta * pr.z;
                v.w = alpha * rows[h][3] + beta * pr.w;
                *reinterpret_cast<float4*>(crow) = v;
            } else {
                float4 v = make_float4(alpha * rows[h][0], alpha * rows[h][1],
                                       alpha * rows[h][2], alpha * rows[h][3]);
                *reinterpret_cast<float4*>(crow) = v;
            }
        }
    }
    #undef LOAD_A
    #undef STORE_A
    #undef LOAD_B
    #undef STORE_B
}

// ---------------------------------------------------------------------------
extern "C" void kernel_launch(void* const* d_in, const int* in_sizes, int n_in,
                              void* d_out, int out_size) {
    (void)in_sizes; (void)n_in; (void)out_size;
    const float* x   = (const float*)d_in[0];
    const float* L   = (const float*)d_in[1];
    const float* w1  = (const float*)d_in[2];
    const float* b1  = (const float*)d_in[3];
    const float* w2  = (const float*)d_in[4];
    const float* b2  = (const float*)d_in[5];
    const float* fw1 = (const float*)d_in[6];
    const float* fb1 = (const float*)d_in[7];
    const float* fw2 = (const float*)d_in[8];
    const float* fb2 = (const float*)d_in[9];
    float* out = (float*)d_out;

    float *xk1, *z, *xk2, *y2, *h1;
    cudaGetSymbolAddress((void**)&xk1, g_xk1);
    cudaGetSymbolAddress((void**)&z,   g_z);
    cudaGetSymbolAddress((void**)&xk2, g_xk2);
    cudaGetSymbolAddress((void**)&y2,  g_y2);
    cudaGetSymbolAddress((void**)&h1,  g_h1);

    // 1) x0 = x^T into xk1 slabs (k=0)
    k_xpose<<<192, 256>>>(x, xk1);

    // 2) conv1 Chebyshev recurrence (K=6 -> steps k=1..5), Fin=3
    k_cheby<<<2048, 256>>>(L, xk1, 1, 1.f, 0.f);
    for (int k = 2; k <= 5; k++)
        k_cheby<<<2048, 256>>>(L, xk1, k, 2.f, -1.f);

    // 3) z0 = relu(xk1 @ W1^T + b1)
    k_conv1_lin<<<NROWS / 256, 256>>>(xk1, w1, b1, z);

    // 4) conv2 Chebyshev recurrence (K=5 -> steps k=1..4), Fin=64
    for (int k = 1; k <= 4; k++) {
        const float* zprev = z + (size_t)(k - 1) * ZSLAB;
        const float* zpp   = (k >= 2) ? z + (size_t)(k - 2) * ZSLAB : z;
        float* zk = z + (size_t)k * ZSLAB;
        float alpha = (k == 1) ? 1.f : 2.f;
        float beta  = (k == 1) ? 0.f : -1.f;
        k_gemm<false, false><<<dim3(1, NV / T_BM, BATCH), 256>>>(
            L, NV, (size_t)NV * NV,
            zprev, 64, (size_t)NV * 64,
            zk, 64, (size_t)NV * 64,
            zpp, (size_t)NV * 64,
            alpha, beta, NV);
    }

    // 5) pack z slabs -> xk2 [rows, fin*5+k]
    k_pack2<<<(NROWS * 64) / 256, 256>>>(z, xk2);

    // 6) y2 = relu(xk2 @ W2^T + b2)   [16384,320] -> 128
    k_gemm<true, true><<<dim3(128 / T_BN, NROWS / T_BM, 1), 256>>>(
        xk2, 320, 0, w2, 320, 0, y2, 128, 0, b2, 0, 1.f, 0.f, 320);

    // 7) h1 = relu(y2 @ fc1_w^T + fb1)   [16384,128] -> 512
    k_gemm<true, true><<<dim3(512 / T_BN, NROWS / T_BM, 1), 256>>>(
        y2, 128, 0, fw1, 128, 0, h1, 512, 0, fb1, 0, 1.f, 0.f, 128);

    // 8) out = relu(h1 @ fc2_w^T + fb2)  [16384,512] -> 256
    k_gemm<true, true><<<dim3(256 / T_BN, NROWS / T_BM, 1), 256>>>(
        h1, 512, 0, fw2, 512, 0, out, 256, 0, fb2, 0, 1.f, 0.f, 512);
}

// round 14
// speedup vs baseline: 1.0013x; 1.0013x over previous
#include <cuda_runtime.h>
#include <cuda_bf16.h>

// ---------------------------------------------------------------------------
// GraphConvNet: B=8, V=2048, D=3, CL1(K=6,F=64), CL2(K=5,F=128), FC 512, 256
// fp32 throughout. Chebyshev L-streams at HBM rate; GEMMs via packed f32x2
// with double-buffered smem and pre-duplicated B operands.
// ---------------------------------------------------------------------------

#define BATCH 8
#define NV    2048
#define NROWS (BATCH * NV)      // 16384

// scratch (device globals; no allocation allowed)
// conv1 basis stored as 18 slabs of [NROWS]; slab id = fin*6 + k (torch order)
__device__ float g_xk1[(size_t)18 * NROWS];
__device__ float g_z[(size_t)5 * NROWS * 64];        // conv2 basis slabs z0..z4, [row][64]
__device__ float g_xk2[(size_t)NROWS * 320];         // packed conv2 basis [row][fin*5+k]
__device__ float g_y2[(size_t)NROWS * 128];
__device__ float g_h1[(size_t)NROWS * 512];

#define ZSLAB ((size_t)NROWS * 64)

// ------------------------- f32x2 packed-FMA helpers ------------------------
__device__ __forceinline__ void fma2(unsigned long long& c,
                                     unsigned long long a, unsigned long long b) {
    asm("fma.rn.f32x2 %0, %1, %2, %0;" : "+l"(c) : "l"(a), "l"(b));
}
__device__ __forceinline__ float2 unpk2(unsigned long long v) {
    float2 f;
    asm("mov.b64 {%0, %1}, %2;" : "=f"(f.x), "=f"(f.y) : "l"(v));
    return f;
}

// ------------------------- transpose x [B,D,V] -> xk1 slab (d*6+0) ---------
__global__ void __launch_bounds__(256) k_xpose(const float* __restrict__ x,
                                               float* __restrict__ xk1) {
    int idx = blockIdx.x * 256 + threadIdx.x;           // over 8*3*2048
    if (idx >= BATCH * 3 * NV) return;
    int v = idx & (NV - 1);
    int d = (idx >> 11) % 3;
    int b = idx / (3 * NV);
    xk1[(size_t)(d * 6) * NROWS + b * NV + v] = x[idx];
}

// ------------------------- conv1 Chebyshev step (Fin=3) --------------------
// slab(f,k) <- alpha * L @ slab(f,k-1) + beta * slab(f,k-2), warp per row
__global__ void __launch_bounds__(256) k_cheby(
    const float* __restrict__ L, float* __restrict__ xk,
    int kIdx, float alpha, float beta) {
    __shared__ __align__(16) float sx[3][NV];
    const int tid = threadIdx.x;
    const int b = blockIdx.x >> 8;                       // 256 blocks per batch
    const size_t bV = (size_t)b * NV;

    #pragma unroll
    for (int f = 0; f < 3; f++) {
        const float* src = xk + (size_t)(f * 6 + kIdx - 1) * NROWS + bV;
        for (int c = tid * 4; c < NV; c += 1024)
            *reinterpret_cast<float4*>(&sx[f][c]) =
                *reinterpret_cast<const float4*>(&src[c]);
    }
    __syncthreads();

    const int warp = tid >> 5, lane = tid & 31;
    const int row = blockIdx.x * 8 + warp;               // global row 0..16383
    const float4* Lr = reinterpret_cast<const float4*>(L + (size_t)row * NV);
    float a0 = 0.f, a1 = 0.f, a2 = 0.f;
    #pragma unroll
    for (int it = 0; it < 16; it++) {
        const int c4 = it * 32 + lane;
        const float4 lv = Lr[c4];
        const float4 x0 = reinterpret_cast<const float4*>(sx[0])[c4];
        const float4 x1 = reinterpret_cast<const float4*>(sx[1])[c4];
        const float4 x2 = reinterpret_cast<const float4*>(sx[2])[c4];
        a0 += lv.x * x0.x + lv.y * x0.y + lv.z * x0.z + lv.w * x0.w;
        a1 += lv.x * x1.x + lv.y * x1.y + lv.z * x1.z + lv.w * x1.w;
        a2 += lv.x * x2.x + lv.y * x2.y + lv.z * x2.z + lv.w * x2.w;
    }
    #pragma unroll
    for (int off = 16; off > 0; off >>= 1) {
        a0 += __shfl_down_sync(0xffffffffu, a0, off);
        a1 += __shfl_down_sync(0xffffffffu, a1, off);
        a2 += __shfl_down_sync(0xffffffffu, a2, off);
    }
    if (lane == 0) {
        float acc[3] = {a0, a1, a2};
        #pragma unroll
        for (int f = 0; f < 3; f++) {
            float p = 0.f;
            if (beta != 0.f)
                p = xk[(size_t)(f * 6 + kIdx - 2) * NROWS + row];
            xk[(size_t)(f * 6 + kIdx) * NROWS + row] = alpha * acc[f] + beta * p;
        }
    }
}

// ------------------------- conv1 linear: z0 = relu(xk1 @ W1^T + b1) --------
// thread per row; weights transposed into smem as sW[j][fo]
__global__ void __launch_bounds__(256) k_conv1_lin(
    const float* __restrict__ xk, const float* __restrict__ W,
    const float* __restrict__ bias, float* __restrict__ z0) {
    __shared__ float sW[18 * 64];
    __shared__ float sb[64];
    const int tid = threadIdx.x;
    for (int i = tid; i < 18 * 64; i += 256) {
        int fo = i / 18, j = i % 18;
        sW[j * 64 + fo] = W[i];
    }
    if (tid < 64) sb[tid] = bias[tid];
    __syncthreads();

    const int row = blockIdx.x * 256 + tid;
    float acc[64];
    #pragma unroll
    for (int fo = 0; fo < 64; fo++) acc[fo] = sb[fo];
    #pragma unroll
    for (int j = 0; j < 18; j++) {
        const float xv = xk[(size_t)j * NROWS + row];
        #pragma unroll
        for (int fo = 0; fo < 64; fo++) acc[fo] += xv * sW[j * 64 + fo];
    }
    float* o = z0 + (size_t)row * 64;
    #pragma unroll
    for (int fo = 0; fo < 64; fo += 4) {
        float4 v;
        v.x = acc[fo]     > 0.f ? acc[fo]     : 0.f;
        v.y = acc[fo + 1] > 0.f ? acc[fo + 1] : 0.f;
        v.z = acc[fo + 2] > 0.f ? acc[fo + 2] : 0.f;
        v.w = acc[fo + 3] > 0.f ? acc[fo + 3] : 0.f;
        *reinterpret_cast<float4*>(&o[fo]) = v;
    }
}

// ------------------------- pack conv2 basis into [row, fin*5+k] ------------
__global__ void __launch_bounds__(256) k_pack2(const float* __restrict__ z,
                                               float* __restrict__ xk2) {
    size_t idx = (size_t)blockIdx.x * 256 + threadIdx.x;   // over 16384*64
    size_t row = idx >> 6;
    int fin = (int)(idx & 63);
    float* o = xk2 + row * 320 + fin * 5;
    #pragma unroll
    for (int k = 0; k < 5; k++) o[k] = z[(size_t)k * ZSLAB + idx];
}

// ------------------------- main GEMM tile kernel (v2) ----------------------
// C[M,N] tiles of 128x64, BK=16, double-buffered, B pre-duplicated for f32x2.
// WTRANS: B is W[N,K] row-major (ldb=K), used as B^T.
// RELUB: C = relu(A@B + bias[n]).  else: C = alpha*A@B + beta*P.
#define T_BM 128
#define T_BN 64
#define T_BK 16
#define ASTR 132      // floats per k-row of As (132*4=528B, 16B aligned)
#define BSTR2 66      // float2 per k-row of Bs (66*8=528B, 16B aligned)

template <bool WTRANS, bool RELUB>
__global__ void __launch_bounds__(256, 2) k_gemm(
    const float* __restrict__ A, int lda, size_t strideA,
    const float* __restrict__ B, int ldb, size_t strideB,
    float* __restrict__ C, int ldc, size_t strideC,
    const float* __restrict__ P, size_t strideP,
    float alpha, float beta, int K) {
    __shared__ __align__(16) float  As[2][T_BK * ASTR];
    __shared__ __align__(16) float2 Bs[2][T_BK * BSTR2];

    const int tid = threadIdx.x;
    const int bz = blockIdx.z;
    A += (size_t)bz * strideA;
    B += (size_t)bz * strideB;
    C += (size_t)bz * strideC;
    P += (size_t)bz * strideP;
    const int m0 = blockIdx.y * T_BM;
    const int n0 = blockIdx.x * T_BN;

    const int tx = tid & 15;   // 4 N-cols each
    const int ty = tid >> 4;   // 8 M-rows each

    unsigned long long acc[4][4];
    #pragma unroll
    for (int p = 0; p < 4; p++)
        #pragma unroll
        for (int j = 0; j < 4; j++) acc[p][j] = 0ull;

    const int arow = tid >> 2;           // 0..63
    const int acol = (tid & 3) * 4;      // 0,4,8,12
    const int brow = tid >> 4;           // 0..15
    const int bcol = (tid & 15) * 4;     // 0..60

    // ---- tile load/store helpers (inlined) ----
    #define LOAD_A(kt, v0, v1)                                                  \
        v0 = *reinterpret_cast<const float4*>(A + (size_t)(m0 + arow) * lda + (kt) + acol); \
        v1 = *reinterpret_cast<const float4*>(A + (size_t)(m0 + arow + 64) * lda + (kt) + acol);
    #define STORE_A(buf, v0, v1)                                                \
        As[buf][(acol + 0) * ASTR + arow] = v0.x;                               \
        As[buf][(acol + 1) * ASTR + arow] = v0.y;                               \
        As[buf][(acol + 2) * ASTR + arow] = v0.z;                               \
        As[buf][(acol + 3) * ASTR + arow] = v0.w;                               \
        As[buf][(acol + 0) * ASTR + arow + 64] = v1.x;                          \
        As[buf][(acol + 1) * ASTR + arow + 64] = v1.y;                          \
        As[buf][(acol + 2) * ASTR + arow + 64] = v1.z;                          \
        As[buf][(acol + 3) * ASTR + arow + 64] = v1.w;
    #define LOAD_B(kt, v)                                                       \
        if (WTRANS) v = *reinterpret_cast<const float4*>(B + (size_t)(n0 + arow) * ldb + (kt) + acol); \
        else        v = *reinterpret_cast<const float4*>(B + (size_t)((kt) + brow) * ldb + n0 + bcol);
    #define STORE_B(buf, v)                                                     \
        if (WTRANS) {                                                           \
            Bs[buf][(acol + 0) * BSTR2 + arow] = make_float2(v.x, v.x);         \
            Bs[buf][(acol + 1) * BSTR2 + arow] = make_float2(v.y, v.y);         \
            Bs[buf][(acol + 2) * BSTR2 + arow] = make_float2(v.z, v.z);         \
            Bs[buf][(acol + 3) * BSTR2 + arow] = make_float2(v.w, v.w);         \
        } else {                                                                \
            float4 lo = make_float4(v.x, v.x, v.y, v.y);                        \
            float4 hi = make_float4(v.z, v.z, v.w, v.w);                        \
            *reinterpret_cast<float4*>(&Bs[buf][brow * BSTR2 + bcol])     = lo; \
            *reinterpret_cast<float4*>(&Bs[buf][brow * BSTR2 + bcol + 2]) = hi; \
        }

    // prologue: tile 0 -> buf 0
    {
        float4 a0, a1, bv;
        LOAD_A(0, a0, a1)
        LOAD_B(0, bv)
        STORE_A(0, a0, a1)
        STORE_B(0, bv)
    }
    __syncthreads();

    const int nt = K / T_BK;
    int cur = 0;
    for (int t = 0; t < nt; t++) {
        float4 pa0, pa1, pb;
        const bool has = (t + 1) < nt;
        if (has) {
            const int ktn = (t + 1) * T_BK;
            LOAD_A(ktn, pa0, pa1)
            LOAD_B(ktn, pb)
        }
        const float*  Ac = As[cur];
        const float2* Bc = Bs[cur];
        #pragma unroll
        for (int k = 0; k < T_BK; k++) {
            const float* ap = &Ac[k * ASTR + ty * 8];
            const ulonglong2 a01 = *reinterpret_cast<const ulonglong2*>(ap);
            const ulonglong2 a23 = *reinterpret_cast<const ulonglong2*>(ap + 4);
            const ulonglong2* bp =
                reinterpret_cast<const ulonglong2*>(&Bc[k * BSTR2 + tx * 4]);
            const ulonglong2 b01 = bp[0];
            const ulonglong2 b23 = bp[1];
            fma2(acc[0][0], a01.x, b01.x); fma2(acc[0][1], a01.x, b01.y);
            fma2(acc[0][2], a01.x, b23.x); fma2(acc[0][3], a01.x, b23.y);
            fma2(acc[1][0], a01.y, b01.x); fma2(acc[1][1], a01.y, b01.y);
            fma2(acc[1][2], a01.y, b23.x); fma2(acc[1][3], a01.y, b23.y);
            fma2(acc[2][0], a23.x, b01.x); fma2(acc[2][1], a23.x, b01.y);
            fma2(acc[2][2], a23.x, b23.x); fma2(acc[2][3], a23.x, b23.y);
            fma2(acc[3][0], a23.y, b01.x); fma2(acc[3][1], a23.y, b01.y);
            fma2(acc[3][2], a23.y, b23.x); fma2(acc[3][3], a23.y, b23.y);
        }
        if (has) {
            STORE_A(cur ^ 1, pa0, pa1)
            STORE_B(cur ^ 1, pb)
        }
        __syncthreads();
        cur ^= 1;
    }

    // ---- epilogue ----
    const int gn = n0 + tx * 4;
    #pragma unroll
    for (int p = 0; p < 4; p++) {
        float rows[2][4];
        #pragma unroll
        for (int j = 0; j < 4; j++) {
            float2 f = unpk2(acc[p][j]);
            rows[0][j] = f.x;
            rows[1][j] = f.y;
        }
        #pragma unroll
        for (int h = 0; h < 2; h++) {
            const int gm = m0 + ty * 8 + 2 * p + h;
            float* crow = C + (size_t)gm * ldc + gn;
            if (RELUB) {
                float4 v;
                v.x = rows[h][0] + P[gn + 0];
                v.y = rows[h][1] + P[gn + 1];
                v.z = rows[h][2] + P[gn + 2];
                v.w = rows[h][3] + P[gn + 3];
                v.x = v.x > 0.f ? v.x : 0.f;
                v.y = v.y > 0.f ? v.y : 0.f;
                v.z = v.z > 0.f ? v.z : 0.f;
                v.w = v.w > 0.f ? v.w : 0.f;
                *reinterpret_cast<float4*>(crow) = v;
            } else if (beta != 0.f) {
                const float4 pr = *reinterpret_cast<const float4*>(
                    P + (size_t)gm * ldc + gn);
                float4 v;
                v.x = alpha * rows[h][0] + beta * pr.x;
                v.y = alpha * rows[h][1] + beta * pr.y;
                v.z = alpha * rows[h][2] + beta * pr.z;
                v.w = alpha * rows[h][3] + beta * pr.w;
                *reinterpret_cast<float4*>(crow) = v;
            } else {
                float4 v = make_float4(alpha * rows[h][0], alpha * rows[h][1],
                                       alpha * rows[h][2], alpha * rows[h][3]);
                *reinterpret_cast<float4*>(crow) = v;
            }
        }
    }
    #undef LOAD_A
    #undef STORE_A
    #undef LOAD_B
    #undef STORE_B
}

// ---------------------------------------------------------------------------
extern "C" void kernel_launch(void* const* d_in, const int* in_sizes, int n_in,
                              void* d_out, int out_size) {
    (void)in_sizes; (void)n_in; (void)out_size;
    const float* x   = (const float*)d_in[0];
    const float* L   = (const float*)d_in[1];
    const float* w1  = (const float*)d_in[2];
    const float* b1  = (const float*)d_in[3];
    const float* w2  = (const float*)d_in[4];
    const float* b2  = (const float*)d_in[5];
    const float* fw1 = (const float*)d_in[6];
    const float* fb1 = (const float*)d_in[7];
    const float* fw2 = (const float*)d_in[8];
    const float* fb2 = (const float*)d_in[9];
    float* out = (float*)d_out;

    float *xk1, *z, *xk2, *y2, *h1;
    cudaGetSymbolAddress((void**)&xk1, g_xk1);
    cudaGetSymbolAddress((void**)&z,   g_z);
    cudaGetSymbolAddress((void**)&xk2, g_xk2);
    cudaGetSymbolAddress((void**)&y2,  g_y2);
    cudaGetSymbolAddress((void**)&h1,  g_h1);

    // 1) x0 = x^T into xk1 slabs (k=0)
    k_xpose<<<192, 256>>>(x, xk1);

    // 2) conv1 Chebyshev recurrence (K=6 -> steps k=1..5), Fin=3
    k_cheby<<<2048, 256>>>(L, xk1, 1, 1.f, 0.f);
    for (int k = 2; k <= 5; k++)
        k_cheby<<<2048, 256>>>(L, xk1, k, 2.f, -1.f);

    // 3) z0 = relu(xk1 @ W1^T + b1)
    k_conv1_lin<<<NROWS / 256, 256>>>(xk1, w1, b1, z);

    // 4) conv2 Chebyshev recurrence (K=5 -> steps k=1..4), Fin=64
    for (int k = 1; k <= 4; k++) {
        const float* zprev = z + (size_t)(k - 1) * ZSLAB;
        const float* zpp   = (k >= 2) ? z + (size_t)(k - 2) * ZSLAB : z;
        float* zk = z + (size_t)k * ZSLAB;
        float alpha = (k == 1) ? 1.f : 2.f;
        float beta  = (k == 1) ? 0.f : -1.f;
        k_gemm<false, false><<<dim3(1, NV / T_BM, BATCH), 256>>>(
            L, NV, (size_t)NV * NV,
            zprev, 64, (size_t)NV * 64,
            zk, 64, (size_t)NV * 64,
            zpp, (size_t)NV * 64,
            alpha, beta, NV);
    }

    // 5) pack z slabs -> xk2 [rows, fin*5+k]
    k_pack2<<<(NROWS * 64) / 256, 256>>>(z, xk2);

    // 6) y2 = relu(xk2 @ W2^T + b2)   [16384,320] -> 128
    k_gemm<true, true><<<dim3(128 / T_BN, NROWS / T_BM, 1), 256>>>(
        xk2, 320, 0, w2, 320, 0, y2, 128, 0, b2, 0, 1.f, 0.f, 320);

    // 7) h1 = relu(y2 @ fc1_w^T + fb1)   [16384,128] -> 512
    k_gemm<true, true><<<dim3(512 / T_BN, NROWS / T_BM, 1), 256>>>(
        y2, 128, 0, fw1, 128, 0, h1, 512, 0, fb1, 0, 1.f, 0.f, 128);

    // 8) out = relu(h1 @ fc2_w^T + fb2)  [16384,512] -> 256
    k_gemm<true, true><<<dim3(256 / T_BN, NROWS / T_BM, 1), 256>>>(
        h1, 512, 0, fw2, 512, 0, out, 256, 0, fb2, 0, 1.f, 0.f, 512);
}

// round 17
// speedup vs baseline: 2.1347x; 2.1319x over previous
#include <cuda_runtime.h>
#include <cuda_bf16.h>
#include <cstdint>

// ---------------------------------------------------------------------------
// GraphConvNet: B=8, V=2048, D=3, CL1(K=6,F=64), CL2(K=5,F=128), FC 512, 256
// conv1: fp32 L-streaming. conv2: bf16 hi/lo split via mma.sync (HMMA).
// Dense layers: f32x2 packed-FMA GEMM.
// ---------------------------------------------------------------------------

#define BATCH 8
#define NV    2048
#define NROWS (BATCH * NV)      // 16384

__device__ float g_xk1[(size_t)18 * NROWS];
__device__ float g_z[(size_t)5 * NROWS * 64];
__device__ float g_xk2[(size_t)NROWS * 320];
__device__ float g_y2[(size_t)NROWS * 128];
__device__ float g_h1[(size_t)NROWS * 512];
__device__ unsigned short g_Lhi[(size_t)BATCH * NV * NV];
__device__ unsigned short g_Llo[(size_t)BATCH * NV * NV];
__device__ unsigned short g_zth[(size_t)BATCH * 64 * NV];
__device__ unsigned short g_ztl[(size_t)BATCH * 64 * NV];

#define ZSLAB ((size_t)NROWS * 64)

// ========================= PTX helpers =====================================
__device__ __forceinline__ uint32_t smem_u32(const void* p) {
    uint32_t a;
    asm("{ .reg .u64 t; cvta.to.shared.u64 t, %1; cvt.u32.u64 %0, t; }"
        : "=r"(a) : "l"(p));
    return a;
}
#define CP16(dst, src) \
    asm volatile("cp.async.cg.shared.global [%0], [%1], 16;" :: "r"(dst), "l"(src))
#define CP_COMMIT() asm volatile("cp.async.commit_group;" ::: "memory")
#define CP_WAIT0()  asm volatile("cp.async.wait_group 0;" ::: "memory")

__device__ __forceinline__ void ldsm_x4(uint32_t addr, uint32_t* r) {
    asm volatile("ldmatrix.sync.aligned.m8n8.x4.shared.b16 {%0,%1,%2,%3}, [%4];"
                 : "=r"(r[0]), "=r"(r[1]), "=r"(r[2]), "=r"(r[3]) : "r"(addr));
}
__device__ __forceinline__ void mma16816(float* c, const uint32_t* a,
                                         const uint32_t* b) {
    asm volatile(
        "mma.sync.aligned.m16n8k16.row.col.f32.bf16.bf16.f32 "
        "{%0,%1,%2,%3}, {%4,%5,%6,%7}, {%8,%9}, {%0,%1,%2,%3};"
        : "+f"(c[0]), "+f"(c[1]), "+f"(c[2]), "+f"(c[3])
        : "r"(a[0]), "r"(a[1]), "r"(a[2]), "r"(a[3]), "r"(b[0]), "r"(b[1]));
}

// ------------------------- f32x2 packed-FMA helpers ------------------------
__device__ __forceinline__ unsigned long long pk2(float x, float y) {
    unsigned long long r;
    asm("mov.b64 %0, {%1, %2};" : "=l"(r) : "f"(x), "f"(y));
    return r;
}
__device__ __forceinline__ unsigned long long dup2(float x) {
    unsigned long long r;
    asm("mov.b64 %0, {%1, %1};" : "=l"(r) : "f"(x));
    return r;
}
__device__ __forceinline__ void fma2(unsigned long long& c,
                                     unsigned long long a, unsigned long long b) {
    asm("fma.rn.f32x2 %0, %1, %2, %0;" : "+l"(c) : "l"(a), "l"(b));
}
__device__ __forceinline__ float2 unpk2(unsigned long long v) {
    float2 f;
    asm("mov.b64 {%0, %1}, %2;" : "=f"(f.x), "=f"(f.y) : "l"(v));
    return f;
}

// ========================= small kernels ===================================
__global__ void __launch_bounds__(256) k_splitL(const float* __restrict__ L,
        unsigned short* __restrict__ hi, unsigned short* __restrict__ lo) {
    size_t i = ((size_t)blockIdx.x * 256 + threadIdx.x) * 4;
    float4 v = *reinterpret_cast<const float4*>(L + i);
    __nv_bfloat16 h[4], l[4];
    float f[4] = {v.x, v.y, v.z, v.w};
    #pragma unroll
    for (int j = 0; j < 4; j++) {
        h[j] = __float2bfloat16(f[j]);
        l[j] = __float2bfloat16(f[j] - __bfloat162float(h[j]));
    }
    *reinterpret_cast<uint2*>(hi + i) = *reinterpret_cast<uint2*>(h);
    *reinterpret_cast<uint2*>(lo + i) = *reinterpret_cast<uint2*>(l);
}

// transpose+split z slab [b][2048][64] -> z^T hi/lo bf16 [b][64][2048]
__global__ void __launch_bounds__(256) k_zt(const float* __restrict__ z,
        unsigned short* __restrict__ th, unsigned short* __restrict__ tl) {
    __shared__ float tile[64][65];
    const int b = blockIdx.y;
    const int v0 = blockIdx.x * 64;
    const int tx = threadIdx.x & 63;
    const int tg = threadIdx.x >> 6;
    #pragma unroll
    for (int i = 0; i < 16; i++) {
        int r = i * 4 + tg;
        tile[r][tx] = z[((size_t)b * NV + v0 + r) * 64 + tx];
    }
    __syncthreads();
    #pragma unroll
    for (int i = 0; i < 16; i++) {
        int n = i * 4 + tg;
        float v = tile[tx][n];
        __nv_bfloat16 h = __float2bfloat16(v);
        __nv_bfloat16 l = __float2bfloat16(v - __bfloat162float(h));
        size_t o = ((size_t)b * 64 + n) * NV + v0 + tx;
        th[o] = *reinterpret_cast<unsigned short*>(&h);
        tl[o] = *reinterpret_cast<unsigned short*>(&l);
    }
}

__global__ void __launch_bounds__(256) k_xpose(const float* __restrict__ x,
                                               float* __restrict__ xk1) {
    int idx = blockIdx.x * 256 + threadIdx.x;
    if (idx >= BATCH * 3 * NV) return;
    int v = idx & (NV - 1);
    int d = (idx >> 11) % 3;
    int b = idx / (3 * NV);
    xk1[(size_t)(d * 6) * NROWS + b * NV + v] = x[idx];
}

// conv1 Chebyshev step (Fin=3), warp per row
__global__ void __launch_bounds__(256) k_cheby(
    const float* __restrict__ L, float* __restrict__ xk,
    int kIdx, float alpha, float beta) {
    __shared__ __align__(16) float sx[3][NV];
    const int tid = threadIdx.x;
    const int b = blockIdx.x >> 8;
    const size_t bV = (size_t)b * NV;
    #pragma unroll
    for (int f = 0; f < 3; f++) {
        const float* src = xk + (size_t)(f * 6 + kIdx - 1) * NROWS + bV;
        for (int c = tid * 4; c < NV; c += 1024)
            *reinterpret_cast<float4*>(&sx[f][c]) =
                *reinterpret_cast<const float4*>(&src[c]);
    }
    __syncthreads();
    const int warp = tid >> 5, lane = tid & 31;
    const int row = blockIdx.x * 8 + warp;
    const float4* Lr = reinterpret_cast<const float4*>(L + (size_t)row * NV);
    float a0 = 0.f, a1 = 0.f, a2 = 0.f;
    #pragma unroll
    for (int it = 0; it < 16; it++) {
        const int c4 = it * 32 + lane;
        const float4 lv = Lr[c4];
        const float4 x0 = reinterpret_cast<const float4*>(sx[0])[c4];
        const float4 x1 = reinterpret_cast<const float4*>(sx[1])[c4];
        const float4 x2 = reinterpret_cast<const float4*>(sx[2])[c4];
        a0 += lv.x * x0.x + lv.y * x0.y + lv.z * x0.z + lv.w * x0.w;
        a1 += lv.x * x1.x + lv.y * x1.y + lv.z * x1.z + lv.w * x1.w;
        a2 += lv.x * x2.x + lv.y * x2.y + lv.z * x2.z + lv.w * x2.w;
    }
    #pragma unroll
    for (int off = 16; off > 0; off >>= 1) {
        a0 += __shfl_down_sync(0xffffffffu, a0, off);
        a1 += __shfl_down_sync(0xffffffffu, a1, off);
        a2 += __shfl_down_sync(0xffffffffu, a2, off);
    }
    if (lane == 0) {
        float acc[3] = {a0, a1, a2};
        #pragma unroll
        for (int f = 0; f < 3; f++) {
            float p = 0.f;
            if (beta != 0.f) p = xk[(size_t)(f * 6 + kIdx - 2) * NROWS + row];
            xk[(size_t)(f * 6 + kIdx) * NROWS + row] = alpha * acc[f] + beta * p;
        }
    }
}

__global__ void __launch_bounds__(256) k_conv1_lin(
    const float* __restrict__ xk, const float* __restrict__ W,
    const float* __restrict__ bias, float* __restrict__ z0) {
    __shared__ float sW[18 * 64];
    __shared__ float sb[64];
    const int tid = threadIdx.x;
    for (int i = tid; i < 18 * 64; i += 256) {
        int fo = i / 18, j = i % 18;
        sW[j * 64 + fo] = W[i];
    }
    if (tid < 64) sb[tid] = bias[tid];
    __syncthreads();
    const int row = blockIdx.x * 256 + tid;
    float acc[64];
    #pragma unroll
    for (int fo = 0; fo < 64; fo++) acc[fo] = sb[fo];
    #pragma unroll
    for (int j = 0; j < 18; j++) {
        const float xv = xk[(size_t)j * NROWS + row];
        #pragma unroll
        for (int fo = 0; fo < 64; fo++) acc[fo] += xv * sW[j * 64 + fo];
    }
    float* o = z0 + (size_t)row * 64;
    #pragma unroll
    for (int fo = 0; fo < 64; fo += 4) {
        float4 v;
        v.x = acc[fo]     > 0.f ? acc[fo]     : 0.f;
        v.y = acc[fo + 1] > 0.f ? acc[fo + 1] : 0.f;
        v.z = acc[fo + 2] > 0.f ? acc[fo + 2] : 0.f;
        v.w = acc[fo + 3] > 0.f ? acc[fo + 3] : 0.f;
        *reinterpret_cast<float4*>(&o[fo]) = v;
    }
}

__global__ void __launch_bounds__(256) k_pack2(const float* __restrict__ z,
                                               float* __restrict__ xk2) {
    size_t idx = (size_t)blockIdx.x * 256 + threadIdx.x;
    size_t row = idx >> 6;
    int fin = (int)(idx & 63);
    float* o = xk2 + row * 320 + fin * 5;
    #pragma unroll
    for (int k = 0; k < 5; k++) o[k] = z[(size_t)k * ZSLAB + idx];
}

// ========================= conv2 via mma.sync (HMMA) =======================
// z_k tile = alpha * (L @ z_{k-1}) + beta * z_{k-2}
// A = L rows (bf16 hi/lo, K-major), B = z^T (bf16 hi/lo, [64][2048])
#define BK2   64
#define NT2   (NV / BK2)          // 32
#define BUFSZ 49152               // Ah 16K | Al 16K | Bh 8K | Bl 8K
#define SWZ(x) ((x) ^ (((x) >> 3) & 0x70))

__device__ __forceinline__ void stage2(uint32_t sbuf,
        const unsigned short* __restrict__ Ah, const unsigned short* __restrict__ Al,
        const unsigned short* __restrict__ Bh, const unsigned short* __restrict__ Bl,
        int kt, int tid) {
    #pragma unroll
    for (int i = 0; i < 4; i++) {
        const int cid = i * 256 + tid;            // 0..1023
        const int row = cid >> 3, ch = cid & 7;
        const int sw = SWZ(row * 128 + ch * 16);
        const char* a = reinterpret_cast<const char*>(Ah + (size_t)row * NV + kt) + ch * 16;
        const char* b = reinterpret_cast<const char*>(Al + (size_t)row * NV + kt) + ch * 16;
        CP16(sbuf + sw, a);
        CP16(sbuf + 16384 + sw, b);
    }
    #pragma unroll
    for (int i = 0; i < 2; i++) {
        const int cid = i * 256 + tid;            // 0..511
        const int row = cid >> 3, ch = cid & 7;
        const int sw = SWZ(row * 128 + ch * 16);
        const char* a = reinterpret_cast<const char*>(Bh + (size_t)row * NV + kt) + ch * 16;
        const char* b = reinterpret_cast<const char*>(Bl + (size_t)row * NV + kt) + ch * 16;
        CP16(sbuf + 32768 + sw, a);
        CP16(sbuf + 40960 + sw, b);
    }
}

__global__ void __launch_bounds__(256) k_cheby2_mma(
    const unsigned short* __restrict__ Lhi, const unsigned short* __restrict__ Llo,
    const unsigned short* __restrict__ Bth, const unsigned short* __restrict__ Btl,
    const float* __restrict__ Zm2, float* __restrict__ Zo,
    float alpha, float beta) {
    extern __shared__ __align__(128) char smem[];
    const int tid = threadIdx.x;
    const int wid = tid >> 5, lane = tid & 31;
    const int mt = blockIdx.x;     // 16 M-tiles of 128
    const int b  = blockIdx.y;     // 8 batches
    const int warp_m = wid & 3;    // 4 warps over M (32 rows each)
    const int warp_n = wid >> 2;   // 2 warps over N (32 cols each)
    const uint32_t sb = smem_u32(smem);

    const unsigned short* Ah = Lhi + ((size_t)b * NV + mt * 128) * NV;
    const unsigned short* Al = Llo + ((size_t)b * NV + mt * 128) * NV;
    const unsigned short* Bh = Bth + (size_t)b * 64 * NV;
    const unsigned short* Bl = Btl + (size_t)b * 64 * NV;

    float acc[2][4][4];
    #pragma unroll
    for (int i = 0; i < 2; i++)
        #pragma unroll
        for (int j = 0; j < 4; j++)
            #pragma unroll
            for (int q = 0; q < 4; q++) acc[i][j][q] = 0.f;

    // ldmatrix lane addressing
    const int g = lane >> 3, lr = lane & 7;
    const int a_row = warp_m * 32 + (g & 1) * 8 + lr;   // + mti*16
    const int a_kch = g >> 1;                           // 0/1
    const int b_row = warp_n * 32 + (g >> 1) * 8 + lr;  // + p*16
    const int b_kch = g & 1;

    stage2(sb, Ah, Al, Bh, Bl, 0, tid);
    CP_COMMIT();
    CP_WAIT0();
    __syncthreads();

    for (int t = 0; t < NT2; t++) {
        const uint32_t buf = sb + (t & 1) * BUFSZ;
        if (t + 1 < NT2) {
            stage2(sb + ((t + 1) & 1) * BUFSZ, Ah, Al, Bh, Bl, (t + 1) * BK2, tid);
            CP_COMMIT();
        }
        #pragma unroll
        for (int ks = 0; ks < 4; ks++) {
            uint32_t ah[2][4], al[2][4], bh[2][4], bl[2][4];
            #pragma unroll
            for (int mti = 0; mti < 2; mti++) {
                const int sw = SWZ((a_row + mti * 16) * 128 + (ks * 2 + a_kch) * 16);
                ldsm_x4(buf + sw, ah[mti]);
                ldsm_x4(buf + 16384 + sw, al[mti]);
            }
            #pragma unroll
            for (int p = 0; p < 2; p++) {
                const int sw = SWZ((b_row + p * 16) * 128 + (ks * 2 + b_kch) * 16);
                ldsm_x4(buf + 32768 + sw, bh[p]);
                ldsm_x4(buf + 40960 + sw, bl[p]);
            }
            #pragma unroll
            for (int mti = 0; mti < 2; mti++)
                #pragma unroll
                for (int nt = 0; nt < 4; nt++) {
                    const uint32_t* bhp = &bh[nt >> 1][(nt & 1) * 2];
                    const uint32_t* blp = &bl[nt >> 1][(nt & 1) * 2];
                    mma16816(acc[mti][nt], ah[mti], bhp);
                    mma16816(acc[mti][nt], ah[mti], blp);
                    mma16816(acc[mti][nt], al[mti], bhp);
                }
        }
        if (t + 1 < NT2) CP_WAIT0();
        __syncthreads();
    }

    // epilogue: C frag (m16n8): c[h*2+j] = (row = qr + h*8, col = qc + j)
    const int qr = lane >> 2, qc = (lane & 3) * 2;
    #pragma unroll
    for (int mti = 0; mti < 2; mti++) {
        #pragma unroll
        for (int h = 0; h < 2; h++) {
            const int row = mt * 128 + warp_m * 32 + mti * 16 + qr + h * 8;
            const size_t o = ((size_t)b * NV + row) * 64;
            #pragma unroll
            for (int nt = 0; nt < 4; nt++) {
                const int col = warp_n * 32 + nt * 8 + qc;
                float2 v;
                v.x = alpha * acc[mti][nt][h * 2 + 0];
                v.y = alpha * acc[mti][nt][h * 2 + 1];
                if (beta != 0.f) {
                    const float2 p = *reinterpret_cast<const float2*>(Zm2 + o + col);
                    v.x += beta * p.x;
                    v.y += beta * p.y;
                }
                *reinterpret_cast<float2*>(Zo + o + col) = v;
            }
        }
    }
}

// ========================= dense GEMM (f32x2, known-good) ==================
#define T_BM 128
#define T_BN 64
#define T_BK 16
#define ASTR 132
#define BSTR 68

template <bool WTRANS, bool RELUB>
__global__ void __launch_bounds__(256) k_gemm(
    const float* __restrict__ A, int lda,
    const float* __restrict__ B, int ldb,
    float* __restrict__ C, int ldc,
    const float* __restrict__ P, int K) {
    __shared__ float As[T_BK * ASTR];
    __shared__ float Bs[T_BK * BSTR];
    const int tid = threadIdx.x;
    const int m0 = blockIdx.y * T_BM;
    const int n0 = blockIdx.x * T_BN;
    const int tx = tid & 15;
    const int ty = tid >> 4;

    unsigned long long acc[4][4];
    #pragma unroll
    for (int p = 0; p < 4; p++)
        #pragma unroll
        for (int j = 0; j < 4; j++) acc[p][j] = 0ull;

    const int arow = tid >> 2;
    const int acol = (tid & 3) * 4;
    const int brow = tid >> 4;
    const int bcol = (tid & 15) * 4;

    for (int kt = 0; kt < K; kt += T_BK) {
        #pragma unroll
        for (int r = 0; r < 2; r++) {
            const int gm = m0 + arow + r * 64;
            const float4 v = *reinterpret_cast<const float4*>(
                A + (size_t)gm * lda + kt + acol);
            As[(acol + 0) * ASTR + arow + r * 64] = v.x;
            As[(acol + 1) * ASTR + arow + r * 64] = v.y;
            As[(acol + 2) * ASTR + arow + r * 64] = v.z;
            As[(acol + 3) * ASTR + arow + r * 64] = v.w;
        }
        if (WTRANS) {
            const float4 v = *reinterpret_cast<const float4*>(
                B + (size_t)(n0 + arow) * ldb + kt + acol);
            Bs[(acol + 0) * BSTR + arow] = v.x;
            Bs[(acol + 1) * BSTR + arow] = v.y;
            Bs[(acol + 2) * BSTR + arow] = v.z;
            Bs[(acol + 3) * BSTR + arow] = v.w;
        } else {
            const float4 v = *reinterpret_cast<const float4*>(
                B + (size_t)(kt + brow) * ldb + n0 + bcol);
            *reinterpret_cast<float4*>(&Bs[brow * BSTR + bcol]) = v;
        }
        __syncthreads();
        #pragma unroll
        for (int k = 0; k < T_BK; k++) {
            const float4 a0 = *reinterpret_cast<const float4*>(&As[k * ASTR + ty * 8]);
            const float4 a1 = *reinterpret_cast<const float4*>(&As[k * ASTR + ty * 8 + 4]);
            unsigned long long av[4];
            av[0] = pk2(a0.x, a0.y);
            av[1] = pk2(a0.z, a0.w);
            av[2] = pk2(a1.x, a1.y);
            av[3] = pk2(a1.z, a1.w);
            const float4 b4 = *reinterpret_cast<const float4*>(&Bs[k * BSTR + tx * 4]);
            unsigned long long bv[4];
            bv[0] = dup2(b4.x);
            bv[1] = dup2(b4.y);
            bv[2] = dup2(b4.z);
            bv[3] = dup2(b4.w);
            #pragma unroll
            for (int p = 0; p < 4; p++)
                #pragma unroll
                for (int j = 0; j < 4; j++) fma2(acc[p][j], av[p], bv[j]);
        }
        __syncthreads();
    }

    const int gn = n0 + tx * 4;
    #pragma unroll
    for (int p = 0; p < 4; p++) {
        float rows[2][4];
        #pragma unroll
        for (int j = 0; j < 4; j++) {
            float2 f = unpk2(acc[p][j]);
            rows[0][j] = f.x;
            rows[1][j] = f.y;
        }
        #pragma unroll
        for (int h = 0; h < 2; h++) {
            const int gm = m0 + ty * 8 + 2 * p + h;
            float* crow = C + (size_t)gm * ldc + gn;
            #pragma unroll
            for (int j = 0; j < 4; j++) {
                float v = rows[h][j] + P[gn + j];
                crow[j] = RELUB ? (v > 0.f ? v : 0.f) : v;
            }
        }
    }
}

// ---------------------------------------------------------------------------
extern "C" void kernel_launch(void* const* d_in, const int* in_sizes, int n_in,
                              void* d_out, int out_size) {
    (void)in_sizes; (void)n_in; (void)out_size;
    const float* x   = (const float*)d_in[0];
    const float* L   = (const float*)d_in[1];
    const float* w1  = (const float*)d_in[2];
    const float* b1  = (const float*)d_in[3];
    const float* w2  = (const float*)d_in[4];
    const float* b2  = (const float*)d_in[5];
    const float* fw1 = (const float*)d_in[6];
    const float* fb1 = (const float*)d_in[7];
    const float* fw2 = (const float*)d_in[8];
    const float* fb2 = (const float*)d_in[9];
    float* out = (float*)d_out;

    float *xk1, *z, *xk2, *y2, *h1;
    unsigned short *Lhi, *Llo, *zth, *ztl;
    cudaGetSymbolAddress((void**)&xk1, g_xk1);
    cudaGetSymbolAddress((void**)&z,   g_z);
    cudaGetSymbolAddress((void**)&xk2, g_xk2);
    cudaGetSymbolAddress((void**)&y2,  g_y2);
    cudaGetSymbolAddress((void**)&h1,  g_h1);
    cudaGetSymbolAddress((void**)&Lhi, g_Lhi);
    cudaGetSymbolAddress((void**)&Llo, g_Llo);
    cudaGetSymbolAddress((void**)&zth, g_zth);
    cudaGetSymbolAddress((void**)&ztl, g_ztl);

    cudaFuncSetAttribute(k_cheby2_mma,
                         cudaFuncAttributeMaxDynamicSharedMemorySize, 2 * BUFSZ);

    // 0) split L into bf16 hi/lo
    k_splitL<<<(BATCH * NV * NV) / (256 * 4), 256>>>(L, Lhi, Llo);

    // 1) x0 = x^T into xk1 slabs (k=0)
    k_xpose<<<192, 256>>>(x, xk1);

    // 2) conv1 Chebyshev recurrence (K=6 -> k=1..5), Fin=3
    k_cheby<<<2048, 256>>>(L, xk1, 1, 1.f, 0.f);
    for (int k = 2; k <= 5; k++)
        k_cheby<<<2048, 256>>>(L, xk1, k, 2.f, -1.f);

    // 3) z0 = relu(xk1 @ W1^T + b1)
    k_conv1_lin<<<NROWS / 256, 256>>>(xk1, w1, b1, z);

    // 4) conv2 Chebyshev recurrence via mma.sync (k=1..4)
    for (int k = 1; k <= 4; k++) {
        const float* zprev = z + (size_t)(k - 1) * ZSLAB;
        const float* zpp   = (k >= 2) ? z + (size_t)(k - 2) * ZSLAB : z;
        float* zk = z + (size_t)k * ZSLAB;
        k_zt<<<dim3(NV / 64, BATCH), 256>>>(zprev, zth, ztl);
        k_cheby2_mma<<<dim3(16, BATCH), 256, 2 * BUFSZ>>>(
            Lhi, Llo, zth, ztl, zpp, zk,
            (k == 1) ? 1.f : 2.f, (k == 1) ? 0.f : -1.f);
    }

    // 5) pack z slabs -> xk2
    k_pack2<<<(NROWS * 64) / 256, 256>>>(z, xk2);

    // 6) y2 = relu(xk2 @ W2^T + b2)
    k_gemm<true, true><<<dim3(128 / T_BN, NROWS / T_BM), 256>>>(
        xk2, 320, w2, 320, y2, 128, b2, 320);

    // 7) h1 = relu(y2 @ fc1_w^T + fb1)
    k_gemm<true, true><<<dim3(512 / T_BN, NROWS / T_BM), 256>>>(
        y2, 128, fw1, 128, h1, 512, fb1, 128);

    // 8) out = relu(h1 @ fc2_w^T + fb2)
    k_gemm<true, true><<<dim3(256 / T_BN, NROWS / T_BM), 256>>>(
        h1, 512, fw2, 512, out, 256, fb2, 512);
}